// round 2
// baseline (speedup 1.0000x reference)
#include <cuda_runtime.h>

#define Bc 2
#define Hc 16
#define Sc 2048
#define Dc 64
#define BHc (Bc*Hc)
#define ROWS_PER_CTA 32
#define NWARPS 8
#define TILE 64
#define NTILES (Sc/TILE)
#define KSTRIDE 68   // pad: conflict-free float4 LDS per quarter-warp

__device__ float g_inv[BHc*Sc];

__global__ __launch_bounds__(256, 2)
void attn_main(const float* __restrict__ q, const float* __restrict__ k,
               const float* __restrict__ v, const float* __restrict__ mask,
               float* __restrict__ out, float* __restrict__ attn)
{
    __shared__ float Qs[ROWS_PER_CTA*Dc];   // 8 KB
    __shared__ float Ks[TILE*KSTRIDE];      // 17 KB
    __shared__ float Vs[TILE*Dc];           // 16 KB
    __shared__ float Ms[TILE];

    const int tid  = threadIdx.x;
    const int lane = tid & 31;
    const int w    = tid >> 5;
    const int blk  = blockIdx.x;
    const int bh   = blk / (Sc/ROWS_PER_CTA);
    const int qblk = blk % (Sc/ROWS_PER_CTA);
    const int row0 = qblk * ROWS_PER_CTA;
    const int b    = bh / Hc;

    const size_t qkvBase = (size_t)bh * Sc * Dc;

    // Q tile -> smem (once)
    {
        const float4* qg = (const float4*)(q + qkvBase + (size_t)row0*Dc);
        for (int f = tid; f < ROWS_PER_CTA*Dc/4; f += 256)
            ((float4*)Qs)[f] = qg[f];
    }

    const int r0 = w*4;
    const int c0 = lane, c1 = lane + 32;

    float o0[4] = {0,0,0,0}, o1[4] = {0,0,0,0};
    float dsum[4] = {0,0,0,0};
    const float scale = 0.125f;   // 1/sqrt(64) exactly

    for (int t = 0; t < NTILES; t++) {
        __syncthreads();   // previous tile fully consumed (also orders Qs on t=0)

        // K tile -> smem (stride 68)
        {
            const float4* kg = (const float4*)(k + qkvBase + (size_t)t*TILE*Dc);
            #pragma unroll
            for (int p = 0; p < 4; p++) {
                int f   = tid + p*256;        // float4 index, 1024 total
                int row = f >> 4;
                int col = (f & 15) << 2;
                *(float4*)&Ks[row*KSTRIDE + col] = kg[f];
            }
        }
        // V tile -> smem (linear, stride 64)
        {
            const float4* vg = (const float4*)(v + qkvBase + (size_t)t*TILE*Dc);
            #pragma unroll
            for (int p = 0; p < 4; p++)
                ((float4*)Vs)[tid + p*256] = vg[tid + p*256];
        }
        if (tid < TILE) Ms[tid] = mask[b*Sc + t*TILE + tid];
        __syncthreads();

        // ---- score phase: 4 rows x 2 cols per lane, d blocked by 16 ----
        float s0[4] = {0,0,0,0}, s1[4] = {0,0,0,0};
        #pragma unroll
        for (int db = 0; db < 4; db++) {
            float4 ka[4], kb[4];
            #pragma unroll
            for (int i = 0; i < 4; i++) {
                ka[i] = *(const float4*)&Ks[c0*KSTRIDE + db*16 + i*4];
                kb[i] = *(const float4*)&Ks[c1*KSTRIDE + db*16 + i*4];
            }
            #pragma unroll
            for (int r = 0; r < 4; r++) {
                #pragma unroll
                for (int i = 0; i < 4; i++) {
                    float4 qv = *(const float4*)&Qs[(r0+r)*Dc + db*16 + i*4];
                    s0[r] += qv.x*ka[i].x + qv.y*ka[i].y + qv.z*ka[i].z + qv.w*ka[i].w;
                    s1[r] += qv.x*kb[i].x + qv.y*kb[i].y + qv.z*kb[i].z + qv.w*kb[i].w;
                }
            }
        }

        const float m0 = Ms[c0] * (-1e9f);
        const float m1 = Ms[c1] * (-1e9f);
        float e0[4], e1[4];
        #pragma unroll
        for (int r = 0; r < 4; r++) {
            e0[r] = __expf(s0[r]*scale + m0);   // masked -> exp(-1e9) == 0
            e1[r] = __expf(s1[r]*scale + m1);
            dsum[r] += e0[r] + e1[r];
            size_t arow = ((size_t)bh*Sc + (row0 + r0 + r)) * Sc + (size_t)t*TILE;
            attn[arow + c0] = e0[r];            // unnormalized; kernel 2 rescales
            attn[arow + c1] = e1[r];
        }

        // ---- out phase: lane owns d = {lane, lane+32}; e broadcast via shfl ----
        #pragma unroll 2
        for (int j = 0; j < 32; j++) {
            float va = Vs[j*Dc + lane];
            float vb = Vs[j*Dc + lane + 32];
            float vc = Vs[(j+32)*Dc + lane];
            float vd = Vs[(j+32)*Dc + lane + 32];
            #pragma unroll
            for (int r = 0; r < 4; r++) {
                float ea = __shfl_sync(0xffffffffu, e0[r], j);
                float eb = __shfl_sync(0xffffffffu, e1[r], j);
                o0[r] += ea*va + eb*vc;
                o1[r] += ea*vb + eb*vd;
            }
        }
    }

    // ---- finalize: reduce denom across warp, normalize out, stash 1/denom ----
    #pragma unroll
    for (int r = 0; r < 4; r++) {
        float dtot = dsum[r];
        #pragma unroll
        for (int off = 16; off; off >>= 1)
            dtot += __shfl_xor_sync(0xffffffffu, dtot, off);
        float inv = 1.0f / dtot;
        int grow = row0 + r0 + r;
        out[qkvBase + (size_t)grow*Dc + lane]      = o0[r]*inv;
        out[qkvBase + (size_t)grow*Dc + lane + 32] = o1[r]*inv;
        if (lane == 0) g_inv[bh*Sc + grow] = inv;
    }
}

__global__ __launch_bounds__(256)
void attn_norm(float* __restrict__ attn)
{
    int row = blockIdx.x;
    float inv = g_inv[row];
    float4* p = (float4*)(attn + (size_t)row * Sc);
    int t = threadIdx.x;
    float4 a = p[t];
    a.x *= inv; a.y *= inv; a.z *= inv; a.w *= inv;
    p[t] = a;
    float4 c = p[t + 256];
    c.x *= inv; c.y *= inv; c.z *= inv; c.w *= inv;
    p[t + 256] = c;
}

extern "C" void kernel_launch(void* const* d_in, const int* in_sizes, int n_in,
                              void* d_out, int out_size)
{
    const float* q    = (const float*)d_in[0];
    const float* k    = (const float*)d_in[1];
    const float* v    = (const float*)d_in[2];
    const float* mask = (const float*)d_in[3];

    float* out  = (float*)d_out;                       // [B,H,S,D] first
    float* attn = out + (size_t)Bc*Hc*Sc*Dc;           // then [B,H,S,S]

    attn_main<<<BHc*(Sc/ROWS_PER_CTA), 256>>>(q, k, v, mask, out, attn);
    attn_norm<<<BHc*Sc, 256>>>(attn);
}

// round 3
// speedup vs baseline: 1.0008x; 1.0008x over previous
#include <cuda_runtime.h>

#define Bc 2
#define Hc 16
#define Sc 2048
#define Dc 64
#define BHc (Bc*Hc)
#define ROWS_PER_CTA 32
#define NWARPS 8
#define TILE 64
#define NTILES (Sc/TILE)
#define KSTRIDE 68   // pad: conflict-free float4 LDS per quarter-warp

__device__ float g_inv[BHc*Sc];

__global__ __launch_bounds__(256, 2)
void attn_main(const float* __restrict__ q, const float* __restrict__ k,
               const float* __restrict__ v, const float* __restrict__ mask,
               float* __restrict__ out, float* __restrict__ attn)
{
    __shared__ float Qs[ROWS_PER_CTA*Dc];   // 8 KB
    __shared__ float Ks[TILE*KSTRIDE];      // 17 KB
    __shared__ float Vs[TILE*Dc];           // 16 KB
    __shared__ float Ms[TILE];

    const int tid  = threadIdx.x;
    const int lane = tid & 31;
    const int w    = tid >> 5;
    const int blk  = blockIdx.x;
    const int bh   = blk / (Sc/ROWS_PER_CTA);
    const int qblk = blk % (Sc/ROWS_PER_CTA);
    const int row0 = qblk * ROWS_PER_CTA;
    const int b    = bh / Hc;

    const size_t qkvBase = (size_t)bh * Sc * Dc;

    // Q tile -> smem (once)
    {
        const float4* qg = (const float4*)(q + qkvBase + (size_t)row0*Dc);
        for (int f = tid; f < ROWS_PER_CTA*Dc/4; f += 256)
            ((float4*)Qs)[f] = qg[f];
    }

    const int r0 = w*4;
    const int c0 = lane, c1 = lane + 32;

    float o0[4] = {0,0,0,0}, o1[4] = {0,0,0,0};
    float dsum[4] = {0,0,0,0};
    const float scale = 0.125f;   // 1/sqrt(64) exactly

    for (int t = 0; t < NTILES; t++) {
        __syncthreads();   // previous tile fully consumed (also orders Qs on t=0)

        // K tile -> smem (stride 68)
        {
            const float4* kg = (const float4*)(k + qkvBase + (size_t)t*TILE*Dc);
            #pragma unroll
            for (int p = 0; p < 4; p++) {
                int f   = tid + p*256;        // float4 index, 1024 total
                int row = f >> 4;
                int col = (f & 15) << 2;
                *(float4*)&Ks[row*KSTRIDE + col] = kg[f];
            }
        }
        // V tile -> smem (linear, stride 64)
        {
            const float4* vg = (const float4*)(v + qkvBase + (size_t)t*TILE*Dc);
            #pragma unroll
            for (int p = 0; p < 4; p++)
                ((float4*)Vs)[tid + p*256] = vg[tid + p*256];
        }
        if (tid < TILE) Ms[tid] = mask[b*Sc + t*TILE + tid];
        __syncthreads();

        // ---- score phase: 4 rows x 2 cols per lane, d blocked by 16 ----
        float s0[4] = {0,0,0,0}, s1[4] = {0,0,0,0};
        #pragma unroll
        for (int db = 0; db < 4; db++) {
            float4 ka[4], kb[4];
            #pragma unroll
            for (int i = 0; i < 4; i++) {
                ka[i] = *(const float4*)&Ks[c0*KSTRIDE + db*16 + i*4];
                kb[i] = *(const float4*)&Ks[c1*KSTRIDE + db*16 + i*4];
            }
            #pragma unroll
            for (int r = 0; r < 4; r++) {
                #pragma unroll
                for (int i = 0; i < 4; i++) {
                    float4 qv = *(const float4*)&Qs[(r0+r)*Dc + db*16 + i*4];
                    s0[r] += qv.x*ka[i].x + qv.y*ka[i].y + qv.z*ka[i].z + qv.w*ka[i].w;
                    s1[r] += qv.x*kb[i].x + qv.y*kb[i].y + qv.z*kb[i].z + qv.w*kb[i].w;
                }
            }
        }

        const float m0 = Ms[c0] * (-1e9f);
        const float m1 = Ms[c1] * (-1e9f);
        float e0[4], e1[4];
        #pragma unroll
        for (int r = 0; r < 4; r++) {
            e0[r] = __expf(s0[r]*scale + m0);   // masked -> exp(-1e9) == 0
            e1[r] = __expf(s1[r]*scale + m1);
            dsum[r] += e0[r] + e1[r];
            size_t arow = ((size_t)bh*Sc + (row0 + r0 + r)) * Sc + (size_t)t*TILE;
            attn[arow + c0] = e0[r];            // unnormalized; kernel 2 rescales
            attn[arow + c1] = e1[r];
        }

        // ---- out phase: lane owns d = {lane, lane+32}; e broadcast via shfl ----
        #pragma unroll 2
        for (int j = 0; j < 32; j++) {
            float va = Vs[j*Dc + lane];
            float vb = Vs[j*Dc + lane + 32];
            float vc = Vs[(j+32)*Dc + lane];
            float vd = Vs[(j+32)*Dc + lane + 32];
            #pragma unroll
            for (int r = 0; r < 4; r++) {
                float ea = __shfl_sync(0xffffffffu, e0[r], j);
                float eb = __shfl_sync(0xffffffffu, e1[r], j);
                o0[r] += ea*va + eb*vc;
                o1[r] += ea*vb + eb*vd;
            }
        }
    }

    // ---- finalize: reduce denom across warp, normalize out, stash 1/denom ----
    #pragma unroll
    for (int r = 0; r < 4; r++) {
        float dtot = dsum[r];
        #pragma unroll
        for (int off = 16; off; off >>= 1)
            dtot += __shfl_xor_sync(0xffffffffu, dtot, off);
        float inv = 1.0f / dtot;
        int grow = row0 + r0 + r;
        out[qkvBase + (size_t)grow*Dc + lane]      = o0[r]*inv;
        out[qkvBase + (size_t)grow*Dc + lane + 32] = o1[r]*inv;
        if (lane == 0) g_inv[bh*Sc + grow] = inv;
    }
}

__global__ __launch_bounds__(256)
void attn_norm(float* __restrict__ attn)
{
    int row = blockIdx.x;
    float inv = g_inv[row];
    float4* p = (float4*)(attn + (size_t)row * Sc);
    int t = threadIdx.x;
    float4 a = p[t];
    a.x *= inv; a.y *= inv; a.z *= inv; a.w *= inv;
    p[t] = a;
    float4 c = p[t + 256];
    c.x *= inv; c.y *= inv; c.z *= inv; c.w *= inv;
    p[t + 256] = c;
}

extern "C" void kernel_launch(void* const* d_in, const int* in_sizes, int n_in,
                              void* d_out, int out_size)
{
    const float* q    = (const float*)d_in[0];
    const float* k    = (const float*)d_in[1];
    const float* v    = (const float*)d_in[2];
    const float* mask = (const float*)d_in[3];

    float* out  = (float*)d_out;                       // [B,H,S,D] first
    float* attn = out + (size_t)Bc*Hc*Sc*Dc;           // then [B,H,S,S]

    attn_main<<<BHc*(Sc/ROWS_PER_CTA), 256>>>(q, k, v, mask, out, attn);
    attn_norm<<<BHc*Sc, 256>>>(attn);
}

// round 6
// speedup vs baseline: 2.1771x; 2.1752x over previous
#include <cuda_runtime.h>
#include <cstdint>

#define Bc 2
#define Hc 16
#define Sc 2048
#define Dc 64
#define BHc (Bc*Hc)
#define MT 128
#define NT 128
#define NKV (Sc/NT)
#define THREADS 256
#define KS 68   // smem row stride (floats): conflict-free for all frag patterns

__device__ float g_inv[BHc*Sc];

__device__ __forceinline__ uint32_t f2tf32(float x){
    uint32_t b = __float_as_uint(x);
    return (b + 0x1000u) & 0xFFFFE000u;     // RN to tf32
}
__device__ __forceinline__ void splitf(float x, uint32_t &h, uint32_t &l){
    uint32_t hb = f2tf32(x);
    h = hb;
    l = __float_as_uint(x - __uint_as_float(hb));  // exact residual
}
__device__ __forceinline__ void mma_tf32(float c[4], uint32_t a0,uint32_t a1,uint32_t a2,uint32_t a3,
                                         uint32_t b0,uint32_t b1){
    asm volatile("mma.sync.aligned.m16n8k8.row.col.f32.tf32.tf32.f32 "
        "{%0,%1,%2,%3}, {%4,%5,%6,%7}, {%8,%9}, {%0,%1,%2,%3};"
        : "+f"(c[0]),"+f"(c[1]),"+f"(c[2]),"+f"(c[3])
        : "r"(a0),"r"(a1),"r"(a2),"r"(a3),"r"(b0),"r"(b1));
}

__global__ __launch_bounds__(THREADS, 1)
void attn_tc(const float* __restrict__ q, const float* __restrict__ k,
             const float* __restrict__ v, const float* __restrict__ mask,
             float* __restrict__ out, float* __restrict__ attn)
{
    extern __shared__ float sm[];
    float* Qs  = sm;                 // 128*KS
    float* Khi = Qs  + MT*KS;
    float* Klo = Khi + NT*KS;
    float* Vs  = Klo + NT*KS;
    float* Ms  = Vs  + NT*KS;        // 128

    const int tid  = threadIdx.x;
    const int w    = tid >> 5, lane = tid & 31;
    const int t    = lane & 3, qr = lane >> 2;
    const int bh   = blockIdx.x >> 4;
    const int mt   = blockIdx.x & 15;
    const int row0 = mt * MT;
    const int b    = bh / Hc;
    const size_t qkvBase = (size_t)bh * Sc * Dc;
    const int arow = 16*w + qr;      // warp-private q-row (and +8)

    // ---- Q tile (pre-scaled by 1/8) ----
    {
        const float4* qg = (const float4*)(q + qkvBase + (size_t)row0 * Dc);
        #pragma unroll
        for (int i = 0; i < 8; i++) {
            int f = tid + i*THREADS;
            int row = f >> 4, c4 = (f & 15) << 2;
            float4 x = qg[f];
            x.x *= 0.125f; x.y *= 0.125f; x.z *= 0.125f; x.w *= 0.125f;
            *(float4*)&Qs[row*KS + c4] = x;
        }
    }

    float Co[8][4];
    #pragma unroll
    for (int n = 0; n < 8; n++) { Co[n][0]=Co[n][1]=Co[n][2]=Co[n][3]=0.f; }
    float dsA = 0.f, dsB = 0.f;

    const int srcA = (lane & ~3) | (t >> 1);
    const int srcC = srcA + 2;
    const bool odd = t & 1;

    for (int tile = 0; tile < NKV; tile++) {
        __syncthreads();   // previous tile's smem fully consumed

        // ---- load K (split hi/lo) and V (RN tf32-rounded) ----
        {
            const float4* kg = (const float4*)(k + qkvBase + (size_t)tile*NT*Dc);
            const float4* vg = (const float4*)(v + qkvBase + (size_t)tile*NT*Dc);
            #pragma unroll
            for (int i = 0; i < 8; i++) {
                int f = tid + i*THREADS;
                int row = f >> 4, c4 = (f & 15) << 2;
                float4 x = kg[f];
                float4 h, l;
                h.x = __uint_as_float(f2tf32(x.x)); l.x = x.x - h.x;
                h.y = __uint_as_float(f2tf32(x.y)); l.y = x.y - h.y;
                h.z = __uint_as_float(f2tf32(x.z)); l.z = x.z - h.z;
                h.w = __uint_as_float(f2tf32(x.w)); l.w = x.w - h.w;
                *(float4*)&Khi[row*KS + c4] = h;
                *(float4*)&Klo[row*KS + c4] = l;
                float4 vv = vg[f];
                vv.x = __uint_as_float(f2tf32(vv.x));
                vv.y = __uint_as_float(f2tf32(vv.y));
                vv.z = __uint_as_float(f2tf32(vv.z));
                vv.w = __uint_as_float(f2tf32(vv.w));
                *(float4*)&Vs[row*KS + c4] = vv;
            }
            if (tid < NT) Ms[tid] = mask[b*Sc + tile*NT + tid] * (-1e9f);
        }
        __syncthreads();

        // ---- QK^T: 3-term tf32 (qhi*khi + qhi*klo + qlo*khi) ----
        float S[16][4];
        #pragma unroll
        for (int j = 0; j < 16; j++) { S[j][0]=S[j][1]=S[j][2]=S[j][3]=0.f; }

        #pragma unroll 1
        for (int s = 0; s < 8; s++) {
            float a0f = Qs[arow*KS     + 8*s + t];
            float a1f = Qs[(arow+8)*KS + 8*s + t];
            float a2f = Qs[arow*KS     + 8*s + t + 4];
            float a3f = Qs[(arow+8)*KS + 8*s + t + 4];
            uint32_t ah0,al0,ah1,al1,ah2,al2,ah3,al3;
            splitf(a0f,ah0,al0); splitf(a1f,ah1,al1);
            splitf(a2f,ah2,al2); splitf(a3f,ah3,al3);
            #pragma unroll
            for (int j = 0; j < 16; j++) {
                int krow = 8*j + qr;
                uint32_t bh0 = __float_as_uint(Khi[krow*KS + 8*s + t]);
                uint32_t bh1 = __float_as_uint(Khi[krow*KS + 8*s + t + 4]);
                uint32_t bl0 = __float_as_uint(Klo[krow*KS + 8*s + t]);
                uint32_t bl1 = __float_as_uint(Klo[krow*KS + 8*s + t + 4]);
                mma_tf32(S[j], ah0,ah1,ah2,ah3, bh0,bh1);
                mma_tf32(S[j], ah0,ah1,ah2,ah3, bl0,bl1);
                mma_tf32(S[j], al0,al1,al2,al3, bh0,bh1);
            }
        }

        // ---- epilogue: exp + mask, row-sum, attn store (unnormalized) ----
        float* abase  = attn + ((size_t)bh*Sc + row0 + arow)*Sc + (size_t)tile*NT;
        float* abase8 = abase + (size_t)8*Sc;
        #pragma unroll
        for (int j = 0; j < 16; j++) {
            float2 m = *(float2*)&Ms[8*j + 2*t];
            float e0 = __expf(S[j][0] + m.x);
            float e1 = __expf(S[j][1] + m.y);
            float e2 = __expf(S[j][2] + m.x);
            float e3 = __expf(S[j][3] + m.y);
            dsA += e0 + e1; dsB += e2 + e3;
            *(float2*)&abase[8*j + 2*t]  = make_float2(e0, e1);
            *(float2*)&abase8[8*j + 2*t] = make_float2(e2, e3);
            S[j][0]=e0; S[j][1]=e1; S[j][2]=e2; S[j][3]=e3;
        }

        // ---- PV: A = P (C-frag -> A-frag via intra-warp shfl), 2-term ----
        #pragma unroll
        for (int s = 0; s < 16; s++) {
            float v0, v1, a0f, a1f, a2f, a3f;
            v0 = __shfl_sync(0xffffffffu, S[s][0], srcA);
            v1 = __shfl_sync(0xffffffffu, S[s][1], srcA);
            a0f = odd ? v1 : v0;
            v0 = __shfl_sync(0xffffffffu, S[s][2], srcA);
            v1 = __shfl_sync(0xffffffffu, S[s][3], srcA);
            a1f = odd ? v1 : v0;
            v0 = __shfl_sync(0xffffffffu, S[s][0], srcC);
            v1 = __shfl_sync(0xffffffffu, S[s][1], srcC);
            a2f = odd ? v1 : v0;
            v0 = __shfl_sync(0xffffffffu, S[s][2], srcC);
            v1 = __shfl_sync(0xffffffffu, S[s][3], srcC);
            a3f = odd ? v1 : v0;
            uint32_t ah0,al0,ah1,al1,ah2,al2,ah3,al3;
            splitf(a0f,ah0,al0); splitf(a1f,ah1,al1);
            splitf(a2f,ah2,al2); splitf(a3f,ah3,al3);
            #pragma unroll
            for (int n = 0; n < 8; n++) {
                int vrow = 8*s + t;
                uint32_t b0 = __float_as_uint(Vs[vrow*KS     + 8*n + qr]);
                uint32_t b1 = __float_as_uint(Vs[(vrow+4)*KS + 8*n + qr]);
                mma_tf32(Co[n], ah0,ah1,ah2,ah3, b0,b1);
                mma_tf32(Co[n], al0,al1,al2,al3, b0,b1);
            }
        }
    }

    // ---- finalize: row denominators (quad reduce), normalize out ----
    dsA += __shfl_xor_sync(0xffffffffu, dsA, 1);
    dsA += __shfl_xor_sync(0xffffffffu, dsA, 2);
    dsB += __shfl_xor_sync(0xffffffffu, dsB, 1);
    dsB += __shfl_xor_sync(0xffffffffu, dsB, 2);
    float invA = 1.0f / dsA, invB = 1.0f / dsB;

    float* obase  = out + qkvBase + (size_t)(row0 + arow)*Dc;
    float* obase8 = obase + 8*Dc;
    #pragma unroll
    for (int n = 0; n < 8; n++) {
        *(float2*)&obase[8*n + 2*t]  = make_float2(Co[n][0]*invA, Co[n][1]*invA);
        *(float2*)&obase8[8*n + 2*t] = make_float2(Co[n][2]*invB, Co[n][3]*invB);
    }
    if (t == 0) {
        g_inv[bh*Sc + row0 + arow]     = invA;
        g_inv[bh*Sc + row0 + arow + 8] = invB;
    }
}

__global__ __launch_bounds__(256)
void attn_norm(float* __restrict__ attn)
{
    int row = blockIdx.x;
    float inv = g_inv[row];
    float4* p = (float4*)(attn + (size_t)row * Sc);
    int t = threadIdx.x;
    float4 a = p[t];
    a.x *= inv; a.y *= inv; a.z *= inv; a.w *= inv;
    p[t] = a;
    float4 c = p[t + 256];
    c.x *= inv; c.y *= inv; c.z *= inv; c.w *= inv;
    p[t + 256] = c;
}

extern "C" void kernel_launch(void* const* d_in, const int* in_sizes, int n_in,
                              void* d_out, int out_size)
{
    const float* q    = (const float*)d_in[0];
    const float* k    = (const float*)d_in[1];
    const float* v    = (const float*)d_in[2];
    const float* mask = (const float*)d_in[3];

    float* out  = (float*)d_out;
    float* attn = out + (size_t)Bc*Hc*Sc*Dc;

    const int smemBytes = (4*128*KS + 128) * 4;   // ~139.8 KB
    cudaFuncSetAttribute(attn_tc, cudaFuncAttributeMaxDynamicSharedMemorySize, smemBytes);
    attn_tc<<<BHc*16, THREADS, smemBytes>>>(q, k, v, mask, out, attn);
    attn_norm<<<BHc*Sc, 256>>>(attn);
}

// round 8
// speedup vs baseline: 2.7821x; 1.2779x over previous
#include <cuda_runtime.h>
#include <cstdint>

#define Bc 2
#define Hc 16
#define Sc 2048
#define Dc 64
#define BHc (Bc*Hc)
#define MT 128
#define NT 128
#define NKV (Sc/NT)
#define THREADS 256

// packed-b32 smem layout (units: uint32)
#define KSTR 36           // K row: 32 packed d-pairs + 4 pad  (36%32==4 -> conflict-free)
#define VSTR 72           // V row: 64 d entries + 8 pad       (72%32==8 -> conflict-free)
#define OFF_KHI 0
#define OFF_KLO (OFF_KHI + NT*KSTR)
#define OFF_VHI (OFF_KLO + NT*KSTR)
#define OFF_VLO (OFF_VHI + (NT/2)*VSTR)
#define OFF_MS  (OFF_VLO + (NT/2)*VSTR)
#define SMEM_U32 (OFF_MS + NT)

__device__ float g_inv[BHc*Sc];

__device__ __forceinline__ uint32_t packb(float hi, float lo){
    uint32_t r;
    asm("cvt.rn.bf16x2.f32 %0, %1, %2;" : "=r"(r) : "f"(hi), "f"(lo));
    return r;
}
__device__ __forceinline__ float unpk_lo(uint32_t u){ return __uint_as_float(u << 16); }
__device__ __forceinline__ float unpk_hi(uint32_t u){ return __uint_as_float(u & 0xFFFF0000u); }

// pack pair + exact residual pair (x0 -> low half, x1 -> high half)
__device__ __forceinline__ void split_pair(float x0, float x1, uint32_t &h, uint32_t &l){
    h = packb(x1, x0);
    l = packb(x1 - unpk_hi(h), x0 - unpk_lo(h));
}

__device__ __forceinline__ void mma_bf16(float c[4], uint32_t a0,uint32_t a1,uint32_t a2,uint32_t a3,
                                         uint32_t b0,uint32_t b1){
    asm volatile("mma.sync.aligned.m16n8k16.row.col.f32.bf16.bf16.f32 "
        "{%0,%1,%2,%3}, {%4,%5,%6,%7}, {%8,%9}, {%0,%1,%2,%3};"
        : "+f"(c[0]),"+f"(c[1]),"+f"(c[2]),"+f"(c[3])
        : "r"(a0),"r"(a1),"r"(a2),"r"(a3),"r"(b0),"r"(b1));
}

__global__ __launch_bounds__(THREADS, 1)
void attn_tc(const float* __restrict__ q, const float* __restrict__ k,
             const float* __restrict__ v, const float* __restrict__ mask,
             float* __restrict__ out, float* __restrict__ attn)
{
    extern __shared__ uint32_t smu[];
    uint32_t* Khi = smu + OFF_KHI;
    uint32_t* Klo = smu + OFF_KLO;
    uint32_t* Vhi = smu + OFF_VHI;
    uint32_t* Vlo = smu + OFF_VLO;
    float*    Ms  = (float*)(smu + OFF_MS);

    const int tid  = threadIdx.x;
    const int w    = tid >> 5, lane = tid & 31;
    const int t    = lane & 3, qr = lane >> 2;
    const int bh   = blockIdx.x >> 4;
    const int mt   = blockIdx.x & 15;
    const int row0 = mt * MT;
    const int b    = bh / Hc;
    const size_t qkvBase = (size_t)bh * Sc * Dc;
    const int arow = 16*w + qr;           // warp-private q-row (and +8)

    // ---- Q A-fragments in registers (loaded once, scaled by 1/8, hi/lo split) ----
    uint32_t qhi[4][4], qlo[4][4];
    {
        const float* qp = q + qkvBase + (size_t)row0 * Dc;
        #pragma unroll
        for (int s = 0; s < 4; s++) {
            float2 a = *(const float2*)&qp[(size_t)arow*Dc     + 16*s + 2*t];
            float2 bq= *(const float2*)&qp[(size_t)(arow+8)*Dc + 16*s + 2*t];
            float2 c = *(const float2*)&qp[(size_t)arow*Dc     + 16*s + 2*t + 8];
            float2 d = *(const float2*)&qp[(size_t)(arow+8)*Dc + 16*s + 2*t + 8];
            split_pair(a.x*0.125f, a.y*0.125f, qhi[s][0], qlo[s][0]);
            split_pair(bq.x*0.125f, bq.y*0.125f, qhi[s][1], qlo[s][1]);
            split_pair(c.x*0.125f, c.y*0.125f, qhi[s][2], qlo[s][2]);
            split_pair(d.x*0.125f, d.y*0.125f, qhi[s][3], qlo[s][3]);
        }
    }

    float Co[8][4];
    #pragma unroll
    for (int n = 0; n < 8; n++) { Co[n][0]=Co[n][1]=Co[n][2]=Co[n][3]=0.f; }
    float dsA = 0.f, dsB = 0.f;

    for (int tile = 0; tile < NKV; tile++) {
        __syncthreads();    // previous tile fully consumed

        // ---- K: split hi/lo, pack bf16x2 along d, stride 36 ----
        {
            const float4* kg = (const float4*)(k + qkvBase + (size_t)tile*NT*Dc);
            #pragma unroll
            for (int i = 0; i < 8; i++) {
                int f = tid + i*THREADS;          // 2048 float4 tasks
                int row = f >> 4, c2 = (f & 15) << 1;
                float4 x = kg[f];
                uint32_t h0,l0,h1,l1;
                split_pair(x.x, x.y, h0, l0);
                split_pair(x.z, x.w, h1, l1);
                *(uint2*)&Khi[row*KSTR + c2] = make_uint2(h0, h1);
                *(uint2*)&Klo[row*KSTR + c2] = make_uint2(l0, l1);
            }
        }
        // ---- V: pack adjacent-key pairs per d, 64 entries/row, stride 72 ----
        {
            const float4* vg = (const float4*)(v + qkvBase + (size_t)tile*NT*Dc);
            #pragma unroll
            for (int i = 0; i < 4; i++) {
                int g = tid + i*THREADS;          // 1024 tasks = 64 pairs x 16 d-groups
                int kp = g >> 4, d4 = (g & 15) << 2;
                float4 f0 = vg[kp*32 + (d4>>2)];        // key 2kp
                float4 f1 = vg[kp*32 + 16 + (d4>>2)];   // key 2kp+1
                uint32_t h0,l0,h1,l1,h2,l2,h3,l3;
                split_pair(f0.x, f1.x, h0, l0);   // low half = even key
                split_pair(f0.y, f1.y, h1, l1);
                split_pair(f0.z, f1.z, h2, l2);
                split_pair(f0.w, f1.w, h3, l3);
                *(uint4*)&Vhi[kp*VSTR + d4] = make_uint4(h0,h1,h2,h3);
                *(uint4*)&Vlo[kp*VSTR + d4] = make_uint4(l0,l1,l2,l3);
            }
        }
        if (tid < NT) Ms[tid] = mask[b*Sc + tile*NT + tid] * (-1e9f);
        __syncthreads();

        // ---- QK^T: 3-term bf16 (qhi*khi + qhi*klo + qlo*khi) ----
        float S[16][4];
        #pragma unroll
        for (int j = 0; j < 16; j++) { S[j][0]=S[j][1]=S[j][2]=S[j][3]=0.f; }

        #pragma unroll
        for (int s = 0; s < 4; s++) {
            #pragma unroll
            for (int j = 0; j < 16; j++) {
                const uint32_t* kh = &Khi[(8*j + qr)*KSTR + 8*s + t];
                const uint32_t* kl = &Klo[(8*j + qr)*KSTR + 8*s + t];
                uint32_t bh0 = kh[0], bh1 = kh[4];
                uint32_t bl0 = kl[0], bl1 = kl[4];
                mma_bf16(S[j], qhi[s][0],qhi[s][1],qhi[s][2],qhi[s][3], bh0,bh1);
                mma_bf16(S[j], qhi[s][0],qhi[s][1],qhi[s][2],qhi[s][3], bl0,bl1);
                mma_bf16(S[j], qlo[s][0],qlo[s][1],qlo[s][2],qlo[s][3], bh0,bh1);
            }
        }

        // ---- epilogue: exp + mask, row-sums, attn store (unnormalized) ----
        float* abase  = attn + ((size_t)bh*Sc + row0 + arow)*Sc + (size_t)tile*NT;
        float* abase8 = abase + (size_t)8*Sc;
        #pragma unroll
        for (int j = 0; j < 16; j++) {
            float2 m = *(float2*)&Ms[8*j + 2*t];
            float e0 = __expf(S[j][0] + m.x);
            float e1 = __expf(S[j][1] + m.y);
            float e2 = __expf(S[j][2] + m.x);
            float e3 = __expf(S[j][3] + m.y);
            dsA += e0 + e1; dsB += e2 + e3;
            *(float2*)&abase[8*j + 2*t]  = make_float2(e0, e1);
            *(float2*)&abase8[8*j + 2*t] = make_float2(e2, e3);
            S[j][0]=e0; S[j][1]=e1; S[j][2]=e2; S[j][3]=e3;
        }

        // ---- PV: A = P directly from C-frags (no shfl), 3-term bf16 ----
        #pragma unroll
        for (int s = 0; s < 8; s++) {
            const float* E = S[2*s];
            const float* F = S[2*s+1];
            uint32_t ah0,al0,ah1,al1,ah2,al2,ah3,al3;
            split_pair(E[0], E[1], ah0, al0);
            split_pair(E[2], E[3], ah1, al1);
            split_pair(F[0], F[1], ah2, al2);
            split_pair(F[2], F[3], ah3, al3);
            #pragma unroll
            for (int nb = 0; nb < 8; nb++) {
                const uint32_t* vh = &Vhi[(8*s + t)*VSTR + 8*nb + qr];
                const uint32_t* vl = &Vlo[(8*s + t)*VSTR + 8*nb + qr];
                uint32_t b0h = vh[0], b1h = vh[4*VSTR];
                uint32_t b0l = vl[0], b1l = vl[4*VSTR];
                mma_bf16(Co[nb], ah0,ah1,ah2,ah3, b0h,b1h);
                mma_bf16(Co[nb], ah0,ah1,ah2,ah3, b0l,b1l);
                mma_bf16(Co[nb], al0,al1,al2,al3, b0h,b1h);
            }
        }
    }

    // ---- finalize: quad-reduce denominators, normalize out ----
    dsA += __shfl_xor_sync(0xffffffffu, dsA, 1);
    dsA += __shfl_xor_sync(0xffffffffu, dsA, 2);
    dsB += __shfl_xor_sync(0xffffffffu, dsB, 1);
    dsB += __shfl_xor_sync(0xffffffffu, dsB, 2);
    float invA = 1.0f / dsA, invB = 1.0f / dsB;

    float* obase  = out + qkvBase + (size_t)(row0 + arow)*Dc;
    float* obase8 = obase + 8*Dc;
    #pragma unroll
    for (int n = 0; n < 8; n++) {
        *(float2*)&obase[8*n + 2*t]  = make_float2(Co[n][0]*invA, Co[n][1]*invA);
        *(float2*)&obase8[8*n + 2*t] = make_float2(Co[n][2]*invB, Co[n][3]*invB);
    }
    if (t == 0) {
        g_inv[bh*Sc + row0 + arow]     = invA;
        g_inv[bh*Sc + row0 + arow + 8] = invB;
    }
}

__global__ __launch_bounds__(256)
void attn_norm(float* __restrict__ attn)
{
    int row = blockIdx.x;
    float inv = g_inv[row];
    float4* p = (float4*)(attn + (size_t)row * Sc);
    int t = threadIdx.x;
    float4 a = p[t];
    a.x *= inv; a.y *= inv; a.z *= inv; a.w *= inv;
    p[t] = a;
    float4 c = p[t + 256];
    c.x *= inv; c.y *= inv; c.z *= inv; c.w *= inv;
    p[t + 256] = c;
}

extern "C" void kernel_launch(void* const* d_in, const int* in_sizes, int n_in,
                              void* d_out, int out_size)
{
    const float* q    = (const float*)d_in[0];
    const float* k    = (const float*)d_in[1];
    const float* v    = (const float*)d_in[2];
    const float* mask = (const float*)d_in[3];

    float* out  = (float*)d_out;
    float* attn = out + (size_t)Bc*Hc*Sc*Dc;

    const int smemBytes = SMEM_U32 * 4;    // ~74.2 KB
    cudaFuncSetAttribute(attn_tc, cudaFuncAttributeMaxDynamicSharedMemorySize, smemBytes);
    attn_tc<<<BHc*16, THREADS, smemBytes>>>(q, k, v, mask, out, attn);
    attn_norm<<<BHc*Sc, 256>>>(attn);
}

// round 9
// speedup vs baseline: 2.9675x; 1.0667x over previous
#include <cuda_runtime.h>
#include <cstdint>

#define Bc 2
#define Hc 16
#define Sc 2048
#define Dc 64
#define BHc (Bc*Hc)
#define MT 128
#define NT 128
#define NKV (Sc/NT)
#define THREADS 256

// packed-b32 region (u32 units)
#define KSTR 36           // K row: 32 packed d-pairs + 4 pad  (36%32==4 -> conflict-free)
#define VSTR 72           // V row: 64 d entries + 8 pad       (72%32==8 -> conflict-free)
#define OFF_KHI 0
#define OFF_KLO (OFF_KHI + NT*KSTR)
#define OFF_VHI (OFF_KLO + NT*KSTR)
#define OFF_VLO (OFF_VHI + (NT/2)*VSTR)
#define PACK_U32 (OFF_VLO + (NT/2)*VSTR)          // 18432 u32 = 73728 B

// byte offsets
#define OFF_MASKALL (PACK_U32*4)                   // 73728: float[2048] = 8 KB
#define OFF_RAW     (OFF_MASKALL + Sc*4)           // 81920
#define RAWTILE     32768                          // 128x64 floats
#define OFF_RAWK(st) (OFF_RAW + (st)*2*RAWTILE)
#define OFF_RAWV(st) (OFF_RAW + (st)*2*RAWTILE + RAWTILE)
#define SMEM_BYTES  (OFF_RAW + 4*RAWTILE)          // 212992 B (~208 KB)

__device__ float g_inv[BHc*Sc];

__device__ __forceinline__ uint32_t smem_u32(const void* p){
    uint32_t a;
    asm("{ .reg .u64 t; cvta.to.shared.u64 t, %1; cvt.u32.u64 %0, t; }" : "=r"(a) : "l"(p));
    return a;
}
__device__ __forceinline__ void cp16(uint32_t dst, const void* src){
    asm volatile("cp.async.cg.shared.global [%0], [%1], 16;" :: "r"(dst), "l"(src));
}
#define CP_COMMIT() asm volatile("cp.async.commit_group;" ::: "memory")
#define CP_WAIT0()  asm volatile("cp.async.wait_group 0;" ::: "memory")

__device__ __forceinline__ uint32_t packb(float hi, float lo){
    uint32_t r;
    asm("cvt.rn.bf16x2.f32 %0, %1, %2;" : "=r"(r) : "f"(hi), "f"(lo));
    return r;
}
__device__ __forceinline__ float unpk_lo(uint32_t u){ return __uint_as_float(u << 16); }
__device__ __forceinline__ float unpk_hi(uint32_t u){ return __uint_as_float(u & 0xFFFF0000u); }
__device__ __forceinline__ void split_pair(float x0, float x1, uint32_t &h, uint32_t &l){
    h = packb(x1, x0);
    l = packb(x1 - unpk_hi(h), x0 - unpk_lo(h));
}
__device__ __forceinline__ void mma_bf16(float c[4], uint32_t a0,uint32_t a1,uint32_t a2,uint32_t a3,
                                         uint32_t b0,uint32_t b1){
    asm volatile("mma.sync.aligned.m16n8k16.row.col.f32.bf16.bf16.f32 "
        "{%0,%1,%2,%3}, {%4,%5,%6,%7}, {%8,%9}, {%0,%1,%2,%3};"
        : "+f"(c[0]),"+f"(c[1]),"+f"(c[2]),"+f"(c[3])
        : "r"(a0),"r"(a1),"r"(a2),"r"(a3),"r"(b0),"r"(b1));
}

__global__ __launch_bounds__(THREADS, 1)
void attn_tc(const float* __restrict__ q, const float* __restrict__ k,
             const float* __restrict__ v, const float* __restrict__ mask,
             float* __restrict__ out, float* __restrict__ attn)
{
    extern __shared__ char smem[];
    uint32_t* smu = (uint32_t*)smem;
    uint32_t* Khi = smu + OFF_KHI;
    uint32_t* Klo = smu + OFF_KLO;
    uint32_t* Vhi = smu + OFF_VHI;
    uint32_t* Vlo = smu + OFF_VLO;
    float* MaskAll = (float*)(smem + OFF_MASKALL);
    const uint32_t sb = smem_u32(smem);

    const int tid  = threadIdx.x;
    const int w    = tid >> 5, lane = tid & 31;
    const int t    = lane & 3, qr = lane >> 2;
    const int bh   = blockIdx.x >> 4;
    const int mt   = blockIdx.x & 15;
    const int row0 = mt * MT;
    const int b    = bh / Hc;
    const size_t qkvBase = (size_t)bh * Sc * Dc;
    const int arow = 16*w + qr;           // warp-private q-row (and +8)

    const float4* kg0 = (const float4*)(k + qkvBase);
    const float4* vg0 = (const float4*)(v + qkvBase);

    // ---- prologue: stage tile 0 ----
    {
        uint32_t rk = sb + OFF_RAWK(0), rv = sb + OFF_RAWV(0);
        #pragma unroll
        for (int i = 0; i < 8; i++) {
            int f = tid + i*THREADS;
            cp16(rk + f*16, kg0 + f);
            cp16(rv + f*16, vg0 + f);
        }
        CP_COMMIT();
    }

    // ---- mask row -> smem (premultiplied by -1e9) ----
    {
        const float4* mg = (const float4*)(mask + b*Sc);
        #pragma unroll
        for (int i = 0; i < 2; i++) {
            int f = tid + i*THREADS;
            float4 m = mg[f];
            m.x *= -1e9f; m.y *= -1e9f; m.z *= -1e9f; m.w *= -1e9f;
            ((float4*)MaskAll)[f] = m;
        }
    }

    // ---- Q A-fragments in registers (loaded once, scaled by 1/8, hi/lo split) ----
    uint32_t qhi[4][4], qlo[4][4];
    {
        const float* qp = q + qkvBase + (size_t)row0 * Dc;
        #pragma unroll
        for (int s = 0; s < 4; s++) {
            float2 a = *(const float2*)&qp[(size_t)arow*Dc     + 16*s + 2*t];
            float2 bq= *(const float2*)&qp[(size_t)(arow+8)*Dc + 16*s + 2*t];
            float2 c = *(const float2*)&qp[(size_t)arow*Dc     + 16*s + 2*t + 8];
            float2 d = *(const float2*)&qp[(size_t)(arow+8)*Dc + 16*s + 2*t + 8];
            split_pair(a.x*0.125f, a.y*0.125f, qhi[s][0], qlo[s][0]);
            split_pair(bq.x*0.125f, bq.y*0.125f, qhi[s][1], qlo[s][1]);
            split_pair(c.x*0.125f, c.y*0.125f, qhi[s][2], qlo[s][2]);
            split_pair(d.x*0.125f, d.y*0.125f, qhi[s][3], qlo[s][3]);
        }
    }

    float Co[8][4];
    #pragma unroll
    for (int n = 0; n < 8; n++) { Co[n][0]=Co[n][1]=Co[n][2]=Co[n][3]=0.f; }
    float dsA = 0.f, dsB = 0.f;

    for (int tile = 0; tile < NKV; tile++) {
        const int cur = tile & 1;
        CP_WAIT0();
        __syncthreads();   // staged tile visible; packed buffers free (prev MMA done)

        // ---- issue next tile's staging while this tile computes ----
        if (tile + 1 < NKV) {
            uint32_t rk = sb + OFF_RAWK(cur ^ 1), rv = sb + OFF_RAWV(cur ^ 1);
            const float4* kg = kg0 + (size_t)(tile+1)*NT*Dc/4;
            const float4* vg = vg0 + (size_t)(tile+1)*NT*Dc/4;
            #pragma unroll
            for (int i = 0; i < 8; i++) {
                int f = tid + i*THREADS;
                cp16(rk + f*16, kg + f);
                cp16(rv + f*16, vg + f);
            }
            CP_COMMIT();
        }

        const float4* RawK = (const float4*)(smem + OFF_RAWK(cur));
        const float4* RawV = (const float4*)(smem + OFF_RAWV(cur));

        // ---- K: split hi/lo, pack bf16x2 along d, stride 36 ----
        #pragma unroll
        for (int i = 0; i < 8; i++) {
            int f = tid + i*THREADS;
            int row = f >> 4, c2 = (f & 15) << 1;
            float4 x = RawK[f];
            uint32_t h0,l0,h1,l1;
            split_pair(x.x, x.y, h0, l0);
            split_pair(x.z, x.w, h1, l1);
            *(uint2*)&Khi[row*KSTR + c2] = make_uint2(h0, h1);
            *(uint2*)&Klo[row*KSTR + c2] = make_uint2(l0, l1);
        }
        // ---- V: pack adjacent-key pairs per d, 64 entries/row, stride 72 ----
        #pragma unroll
        for (int i = 0; i < 4; i++) {
            int g = tid + i*THREADS;
            int kp = g >> 4, d4 = (g & 15) << 2;
            float4 f0 = RawV[kp*32 + (d4>>2)];        // key 2kp
            float4 f1 = RawV[kp*32 + 16 + (d4>>2)];   // key 2kp+1
            uint32_t h0,l0,h1,l1,h2,l2,h3,l3;
            split_pair(f0.x, f1.x, h0, l0);   // low half = even key
            split_pair(f0.y, f1.y, h1, l1);
            split_pair(f0.z, f1.z, h2, l2);
            split_pair(f0.w, f1.w, h3, l3);
            *(uint4*)&Vhi[kp*VSTR + d4] = make_uint4(h0,h1,h2,h3);
            *(uint4*)&Vlo[kp*VSTR + d4] = make_uint4(l0,l1,l2,l3);
        }
        __syncthreads();

        // ---- QK^T: 3-term bf16 (qhi*khi + qhi*klo + qlo*khi) ----
        float S[16][4];
        #pragma unroll
        for (int j = 0; j < 16; j++) { S[j][0]=S[j][1]=S[j][2]=S[j][3]=0.f; }

        #pragma unroll
        for (int s = 0; s < 4; s++) {
            #pragma unroll
            for (int j = 0; j < 16; j++) {
                const uint32_t* kh = &Khi[(8*j + qr)*KSTR + 8*s + t];
                const uint32_t* kl = &Klo[(8*j + qr)*KSTR + 8*s + t];
                uint32_t bh0 = kh[0], bh1 = kh[4];
                uint32_t bl0 = kl[0], bl1 = kl[4];
                mma_bf16(S[j], qhi[s][0],qhi[s][1],qhi[s][2],qhi[s][3], bh0,bh1);
                mma_bf16(S[j], qhi[s][0],qhi[s][1],qhi[s][2],qhi[s][3], bl0,bl1);
                mma_bf16(S[j], qlo[s][0],qlo[s][1],qlo[s][2],qlo[s][3], bh0,bh1);
            }
        }

        // ---- epilogue: exp + mask, row-sums, attn store (unnormalized) ----
        const float* Ms = MaskAll + tile*NT;
        float* abase  = attn + ((size_t)bh*Sc + row0 + arow)*Sc + (size_t)tile*NT;
        float* abase8 = abase + (size_t)8*Sc;
        #pragma unroll
        for (int j = 0; j < 16; j++) {
            float2 m = *(float2*)&Ms[8*j + 2*t];
            float e0 = __expf(S[j][0] + m.x);
            float e1 = __expf(S[j][1] + m.y);
            float e2 = __expf(S[j][2] + m.x);
            float e3 = __expf(S[j][3] + m.y);
            dsA += e0 + e1; dsB += e2 + e3;
            *(float2*)&abase[8*j + 2*t]  = make_float2(e0, e1);
            *(float2*)&abase8[8*j + 2*t] = make_float2(e2, e3);
            S[j][0]=e0; S[j][1]=e1; S[j][2]=e2; S[j][3]=e3;
        }

        // ---- PV: A = P directly from C-frags (no shfl), 3-term bf16 ----
        #pragma unroll
        for (int s = 0; s < 8; s++) {
            const float* E = S[2*s];
            const float* F = S[2*s+1];
            uint32_t ah0,al0,ah1,al1,ah2,al2,ah3,al3;
            split_pair(E[0], E[1], ah0, al0);
            split_pair(E[2], E[3], ah1, al1);
            split_pair(F[0], F[1], ah2, al2);
            split_pair(F[2], F[3], ah3, al3);
            #pragma unroll
            for (int nb = 0; nb < 8; nb++) {
                const uint32_t* vh = &Vhi[(8*s + t)*VSTR + 8*nb + qr];
                const uint32_t* vl = &Vlo[(8*s + t)*VSTR + 8*nb + qr];
                uint32_t b0h = vh[0], b1h = vh[4*VSTR];
                uint32_t b0l = vl[0], b1l = vl[4*VSTR];
                mma_bf16(Co[nb], ah0,ah1,ah2,ah3, b0h,b1h);
                mma_bf16(Co[nb], ah0,ah1,ah2,ah3, b0l,b1l);
                mma_bf16(Co[nb], al0,al1,al2,al3, b0h,b1h);
            }
        }
    }

    // ---- finalize: quad-reduce denominators, normalize out ----
    dsA += __shfl_xor_sync(0xffffffffu, dsA, 1);
    dsA += __shfl_xor_sync(0xffffffffu, dsA, 2);
    dsB += __shfl_xor_sync(0xffffffffu, dsB, 1);
    dsB += __shfl_xor_sync(0xffffffffu, dsB, 2);
    float invA = 1.0f / dsA, invB = 1.0f / dsB;

    float* obase  = out + qkvBase + (size_t)(row0 + arow)*Dc;
    float* obase8 = obase + 8*Dc;
    #pragma unroll
    for (int n = 0; n < 8; n++) {
        *(float2*)&obase[8*n + 2*t]  = make_float2(Co[n][0]*invA, Co[n][1]*invA);
        *(float2*)&obase8[8*n + 2*t] = make_float2(Co[n][2]*invB, Co[n][3]*invB);
    }
    if (t == 0) {
        g_inv[bh*Sc + row0 + arow]     = invA;
        g_inv[bh*Sc + row0 + arow + 8] = invB;
    }
}

__global__ __launch_bounds__(256)
void attn_norm(float* __restrict__ attn)
{
    int row = blockIdx.x;
    float inv = g_inv[row];
    float4* p = (float4*)(attn + (size_t)row * Sc);
    int t = threadIdx.x;
    float4 a = p[t];
    a.x *= inv; a.y *= inv; a.z *= inv; a.w *= inv;
    p[t] = a;
    float4 c = p[t + 256];
    c.x *= inv; c.y *= inv; c.z *= inv; c.w *= inv;
    p[t + 256] = c;
}

extern "C" void kernel_launch(void* const* d_in, const int* in_sizes, int n_in,
                              void* d_out, int out_size)
{
    const float* q    = (const float*)d_in[0];
    const float* k    = (const float*)d_in[1];
    const float* v    = (const float*)d_in[2];
    const float* mask = (const float*)d_in[3];

    float* out  = (float*)d_out;
    float* attn = out + (size_t)Bc*Hc*Sc*Dc;

    cudaFuncSetAttribute(attn_tc, cudaFuncAttributeMaxDynamicSharedMemorySize, SMEM_BYTES);
    attn_tc<<<BHc*16, THREADS, SMEM_BYTES>>>(q, k, v, mask, out, attn);
    attn_norm<<<BHc*Sc, 256>>>(attn);
}

// round 10
// speedup vs baseline: 3.0329x; 1.0220x over previous
#include <cuda_runtime.h>
#include <cstdint>

#define Bc 2
#define Hc 16
#define Sc 2048
#define Dc 64
#define BHc (Bc*Hc)
#define MT 128
#define NT 128
#define NKV (Sc/NT)
#define THREADS 256

// packed strides (u32 units)
#define KSTR 36           // K row: 32 packed d-pairs + 4 pad  (36%32==4 -> conflict-free)
#define VSTR 72           // V row: 64 d entries + 8 pad       (72%32==8 -> conflict-free)

// smem byte layout: two stages of [Khi|Klo|Vhi|Vlo], then mask
#define KBYTES (NT*KSTR*4)          // 18432
#define VBYTES ((NT/2)*VSTR*4)      // 18432
#define PSTAGE (2*KBYTES + 2*VBYTES)            // 73728 per stage
#define OFF_MASKALL (2*PSTAGE)                   // 147456
#define SMEM_BYTES (OFF_MASKALL + Sc*4)          // 155648

__device__ float g_inv[BHc*Sc];
// pre-split packed bf16 buffers (32 MB total, static scratch)
__device__ uint32_t g_khi[(size_t)BHc*Sc*32];
__device__ uint32_t g_klo[(size_t)BHc*Sc*32];
__device__ uint32_t g_vhi[(size_t)BHc*(Sc/2)*64];
__device__ uint32_t g_vlo[(size_t)BHc*(Sc/2)*64];

__device__ __forceinline__ uint32_t smem_u32(const void* p){
    uint32_t a;
    asm("{ .reg .u64 t; cvta.to.shared.u64 t, %1; cvt.u32.u64 %0, t; }" : "=r"(a) : "l"(p));
    return a;
}
__device__ __forceinline__ void cp16(uint32_t dst, const void* src){
    asm volatile("cp.async.cg.shared.global [%0], [%1], 16;" :: "r"(dst), "l"(src));
}
#define CP_COMMIT() asm volatile("cp.async.commit_group;" ::: "memory")
#define CP_WAIT0()  asm volatile("cp.async.wait_group 0;" ::: "memory")

__device__ __forceinline__ uint32_t packb(float hi, float lo){
    uint32_t r;
    asm("cvt.rn.bf16x2.f32 %0, %1, %2;" : "=r"(r) : "f"(hi), "f"(lo));
    return r;
}
__device__ __forceinline__ float unpk_lo(uint32_t u){ return __uint_as_float(u << 16); }
__device__ __forceinline__ float unpk_hi(uint32_t u){ return __uint_as_float(u & 0xFFFF0000u); }
__device__ __forceinline__ void split_pair(float x0, float x1, uint32_t &h, uint32_t &l){
    h = packb(x1, x0);
    l = packb(x1 - unpk_hi(h), x0 - unpk_lo(h));
}
__device__ __forceinline__ void mma_bf16(float c[4], uint32_t a0,uint32_t a1,uint32_t a2,uint32_t a3,
                                         uint32_t b0,uint32_t b1){
    asm volatile("mma.sync.aligned.m16n8k16.row.col.f32.bf16.bf16.f32 "
        "{%0,%1,%2,%3}, {%4,%5,%6,%7}, {%8,%9}, {%0,%1,%2,%3};"
        : "+f"(c[0]),"+f"(c[1]),"+f"(c[2]),"+f"(c[3])
        : "r"(a0),"r"(a1),"r"(a2),"r"(a3),"r"(b0),"r"(b1));
}

// ---- prep: fp32 K/V -> packed bf16 hi/lo global buffers ----
__global__ __launch_bounds__(256)
void prep_split(const float* __restrict__ k, const float* __restrict__ v)
{
    int idx = blockIdx.x*256 + threadIdx.x;
    if (idx < BHc*Sc*16) {
        // K: one float4 (4 d-values) -> 2 packed u32 hi + 2 lo
        float4 x = ((const float4*)k)[(size_t)idx];
        uint32_t h0,l0,h1,l1;
        split_pair(x.x, x.y, h0, l0);
        split_pair(x.z, x.w, h1, l1);
        size_t o = ((size_t)(idx >> 4) << 5) + (size_t)((idx & 15) << 1);  // row*32 + c4*2
        *(uint2*)&g_khi[o] = make_uint2(h0, h1);
        *(uint2*)&g_klo[o] = make_uint2(l0, l1);
    } else {
        int vi = idx - BHc*Sc*16;
        if (vi < BHc*(Sc/2)*16) {
            int kp_g = vi >> 4;        // global key-pair index (bh*1024 + kp)
            int ch   = vi & 15;        // d4 group
            const float4* vp = (const float4*)v;
            float4 f0 = vp[(size_t)kp_g*32 + ch];        // key 2kp
            float4 f1 = vp[(size_t)kp_g*32 + 16 + ch];   // key 2kp+1
            uint32_t h0,l0,h1,l1,h2,l2,h3,l3;
            split_pair(f0.x, f1.x, h0, l0);   // low half = even key
            split_pair(f0.y, f1.y, h1, l1);
            split_pair(f0.z, f1.z, h2, l2);
            split_pair(f0.w, f1.w, h3, l3);
            size_t o = (size_t)kp_g*64 + (size_t)ch*4;
            *(uint4*)&g_vhi[o] = make_uint4(h0,h1,h2,h3);
            *(uint4*)&g_vlo[o] = make_uint4(l0,l1,l2,l3);
        }
    }
}

// stage one tile of packed K/V into smem stage buffer via cp.async
__device__ __forceinline__ void stage_tile(uint32_t sb, int stage, int bh, int tile, int tid)
{
    const uint32_t dstK = sb + stage*PSTAGE;
    #pragma unroll
    for (int i = 0; i < 8; i++) {
        int f = tid + i*THREADS;            // 2048 K chunks (hi then lo)
        int hl = f >> 10, r = f & 1023;
        int row = r >> 3, ch = r & 7;
        const uint32_t* src = (hl ? g_klo : g_khi)
            + ((size_t)(bh*Sc + tile*NT + row))*32 + (size_t)ch*4;
        cp16(dstK + hl*KBYTES + row*(KSTR*4) + ch*16, src);
    }
    const uint32_t dstV = sb + stage*PSTAGE + 2*KBYTES;
    #pragma unroll
    for (int i = 0; i < 8; i++) {
        int f = tid + i*THREADS;            // 2048 V chunks (hi then lo)
        int hl = f >> 10, r = f & 1023;
        int kp = r >> 4, ch = r & 15;
        const uint32_t* src = (hl ? g_vlo : g_vhi)
            + ((size_t)(bh*(Sc/2) + tile*(NT/2) + kp))*64 + (size_t)ch*4;
        cp16(dstV + hl*VBYTES + kp*(VSTR*4) + ch*16, src);
    }
}

__global__ __launch_bounds__(THREADS, 1)
void attn_tc(const float* __restrict__ q, const float* __restrict__ mask,
             float* __restrict__ out, float* __restrict__ attn)
{
    extern __shared__ char smem[];
    float* MaskAll = (float*)(smem + OFF_MASKALL);
    const uint32_t sb = smem_u32(smem);

    const int tid  = threadIdx.x;
    const int w    = tid >> 5, lane = tid & 31;
    const int t    = lane & 3, qr = lane >> 2;
    const int bh   = blockIdx.x >> 4;
    const int mt   = blockIdx.x & 15;
    const int row0 = mt * MT;
    const int b    = bh / Hc;
    const size_t qkvBase = (size_t)bh * Sc * Dc;
    const int arow = 16*w + qr;           // warp-private q-row (and +8)

    // ---- prologue: stage tile 0 ----
    stage_tile(sb, 0, bh, 0, tid);
    CP_COMMIT();

    // ---- mask row -> smem (premultiplied by -1e9) ----
    {
        const float4* mg = (const float4*)(mask + b*Sc);
        #pragma unroll
        for (int i = 0; i < 2; i++) {
            int f = tid + i*THREADS;
            float4 m = mg[f];
            m.x *= -1e9f; m.y *= -1e9f; m.z *= -1e9f; m.w *= -1e9f;
            ((float4*)MaskAll)[f] = m;
        }
    }

    // ---- Q A-fragments in registers (loaded once, scaled by 1/8, hi/lo split) ----
    uint32_t qhi[4][4], qlo[4][4];
    {
        const float* qp = q + qkvBase + (size_t)row0 * Dc;
        #pragma unroll
        for (int s = 0; s < 4; s++) {
            float2 a = *(const float2*)&qp[(size_t)arow*Dc     + 16*s + 2*t];
            float2 bq= *(const float2*)&qp[(size_t)(arow+8)*Dc + 16*s + 2*t];
            float2 c = *(const float2*)&qp[(size_t)arow*Dc     + 16*s + 2*t + 8];
            float2 d = *(const float2*)&qp[(size_t)(arow+8)*Dc + 16*s + 2*t + 8];
            split_pair(a.x*0.125f, a.y*0.125f, qhi[s][0], qlo[s][0]);
            split_pair(bq.x*0.125f, bq.y*0.125f, qhi[s][1], qlo[s][1]);
            split_pair(c.x*0.125f, c.y*0.125f, qhi[s][2], qlo[s][2]);
            split_pair(d.x*0.125f, d.y*0.125f, qhi[s][3], qlo[s][3]);
        }
    }

    float Co[8][4];
    #pragma unroll
    for (int n = 0; n < 8; n++) { Co[n][0]=Co[n][1]=Co[n][2]=Co[n][3]=0.f; }
    float dsA = 0.f, dsB = 0.f;

    for (int tile = 0; tile < NKV; tile++) {
        const int cur = tile & 1;
        CP_WAIT0();
        __syncthreads();   // staged tile visible; prefetch buffer free (prev PV done)

        if (tile + 1 < NKV) {
            stage_tile(sb, cur ^ 1, bh, tile + 1, tid);
            CP_COMMIT();
        }

        const uint32_t* Khi = (const uint32_t*)(smem + cur*PSTAGE);
        const uint32_t* Klo = Khi + KBYTES/4;
        const uint32_t* Vhi = Khi + 2*(KBYTES/4);
        const uint32_t* Vlo = Khi + 2*(KBYTES/4) + VBYTES/4;

        // ---- QK^T: 3-term bf16 (qhi*khi + qhi*klo + qlo*khi) ----
        float S[16][4];
        #pragma unroll
        for (int j = 0; j < 16; j++) { S[j][0]=S[j][1]=S[j][2]=S[j][3]=0.f; }

        #pragma unroll
        for (int s = 0; s < 4; s++) {
            #pragma unroll
            for (int j = 0; j < 16; j++) {
                const uint32_t* kh = &Khi[(8*j + qr)*KSTR + 8*s + t];
                const uint32_t* kl = &Klo[(8*j + qr)*KSTR + 8*s + t];
                uint32_t bh0 = kh[0], bh1 = kh[4];
                uint32_t bl0 = kl[0], bl1 = kl[4];
                mma_bf16(S[j], qhi[s][0],qhi[s][1],qhi[s][2],qhi[s][3], bh0,bh1);
                mma_bf16(S[j], qhi[s][0],qhi[s][1],qhi[s][2],qhi[s][3], bl0,bl1);
                mma_bf16(S[j], qlo[s][0],qlo[s][1],qlo[s][2],qlo[s][3], bh0,bh1);
            }
        }

        // ---- epilogue: exp + mask, row-sums, attn store (unnormalized) ----
        const float* Ms = MaskAll + tile*NT;
        float* abase  = attn + ((size_t)bh*Sc + row0 + arow)*Sc + (size_t)tile*NT;
        float* abase8 = abase + (size_t)8*Sc;
        #pragma unroll
        for (int j = 0; j < 16; j++) {
            float2 m = *(float2*)&Ms[8*j + 2*t];
            float e0 = __expf(S[j][0] + m.x);
            float e1 = __expf(S[j][1] + m.y);
            float e2 = __expf(S[j][2] + m.x);
            float e3 = __expf(S[j][3] + m.y);
            dsA += e0 + e1; dsB += e2 + e3;
            *(float2*)&abase[8*j + 2*t]  = make_float2(e0, e1);
            *(float2*)&abase8[8*j + 2*t] = make_float2(e2, e3);
            S[j][0]=e0; S[j][1]=e1; S[j][2]=e2; S[j][3]=e3;
        }

        // ---- PV: A = P directly from C-frags (no shfl), 3-term bf16 ----
        #pragma unroll
        for (int s = 0; s < 8; s++) {
            const float* E = S[2*s];
            const float* F = S[2*s+1];
            uint32_t ah0,al0,ah1,al1,ah2,al2,ah3,al3;
            split_pair(E[0], E[1], ah0, al0);
            split_pair(E[2], E[3], ah1, al1);
            split_pair(F[0], F[1], ah2, al2);
            split_pair(F[2], F[3], ah3, al3);
            #pragma unroll
            for (int nb = 0; nb < 8; nb++) {
                const uint32_t* vh = &Vhi[(8*s + t)*VSTR + 8*nb + qr];
                const uint32_t* vl = &Vlo[(8*s + t)*VSTR + 8*nb + qr];
                uint32_t b0h = vh[0], b1h = vh[4*VSTR];
                uint32_t b0l = vl[0], b1l = vl[4*VSTR];
                mma_bf16(Co[nb], ah0,ah1,ah2,ah3, b0h,b1h);
                mma_bf16(Co[nb], ah0,ah1,ah2,ah3, b0l,b1l);
                mma_bf16(Co[nb], al0,al1,al2,al3, b0h,b1h);
            }
        }
    }

    // ---- finalize: quad-reduce denominators, normalize out ----
    dsA += __shfl_xor_sync(0xffffffffu, dsA, 1);
    dsA += __shfl_xor_sync(0xffffffffu, dsA, 2);
    dsB += __shfl_xor_sync(0xffffffffu, dsB, 1);
    dsB += __shfl_xor_sync(0xffffffffu, dsB, 2);
    float invA = 1.0f / dsA, invB = 1.0f / dsB;

    float* obase  = out + qkvBase + (size_t)(row0 + arow)*Dc;
    float* obase8 = obase + 8*Dc;
    #pragma unroll
    for (int n = 0; n < 8; n++) {
        *(float2*)&obase[8*n + 2*t]  = make_float2(Co[n][0]*invA, Co[n][1]*invA);
        *(float2*)&obase8[8*n + 2*t] = make_float2(Co[n][2]*invB, Co[n][3]*invB);
    }
    if (t == 0) {
        g_inv[bh*Sc + row0 + arow]     = invA;
        g_inv[bh*Sc + row0 + arow + 8] = invB;
    }
}

__global__ __launch_bounds__(256)
void attn_norm(float* __restrict__ attn)
{
    int row = blockIdx.x;
    float inv = g_inv[row];
    float4* p = (float4*)(attn + (size_t)row * Sc);
    int t = threadIdx.x;
    float4 a = p[t];
    a.x *= inv; a.y *= inv; a.z *= inv; a.w *= inv;
    p[t] = a;
    float4 c = p[t + 256];
    c.x *= inv; c.y *= inv; c.z *= inv; c.w *= inv;
    p[t + 256] = c;
}

extern "C" void kernel_launch(void* const* d_in, const int* in_sizes, int n_in,
                              void* d_out, int out_size)
{
    const float* q    = (const float*)d_in[0];
    const float* k    = (const float*)d_in[1];
    const float* v    = (const float*)d_in[2];
    const float* mask = (const float*)d_in[3];

    float* out  = (float*)d_out;
    float* attn = out + (size_t)Bc*Hc*Sc*Dc;

    const int prepTasks = BHc*Sc*16 + BHc*(Sc/2)*16;   // 1,572,864
    prep_split<<<(prepTasks + 255)/256, 256>>>(k, v);

    cudaFuncSetAttribute(attn_tc, cudaFuncAttributeMaxDynamicSharedMemorySize, SMEM_BYTES);
    attn_tc<<<BHc*16, THREADS, SMEM_BYTES>>>(q, mask, out, attn);
    attn_norm<<<BHc*Sc, 256>>>(attn);
}

// round 11
// speedup vs baseline: 3.1295x; 1.0318x over previous
#include <cuda_runtime.h>
#include <cstdint>

#define Bc 2
#define Hc 16
#define Sc 2048
#define Dc 64
#define BHc (Bc*Hc)
#define MT 128
#define NT 128
#define NKV (Sc/NT)
#define THREADS 256

// packed strides (u32 units)
#define KSTR 36           // K row: 32 packed d-pairs + 4 pad  (36%32==4 -> conflict-free)
#define VSTR 72           // V row: 64 d entries + 8 pad       (72%32==8 -> conflict-free)

// smem byte layout: two stages of [Khi|Klo|Vhi|Vlo], then mask
#define KBYTES (NT*KSTR*4)          // 18432
#define VBYTES ((NT/2)*VSTR*4)      // 18432
#define PSTAGE (2*KBYTES + 2*VBYTES)            // 73728 per stage
#define OFF_MASKALL (2*PSTAGE)                   // 147456
#define SMEM_BYTES (OFF_MASKALL + Sc*4)          // 155648

__device__ float g_inv[BHc*Sc];
// pre-split packed bf16 buffers (32 MB total, static scratch)
__device__ uint32_t g_khi[(size_t)BHc*Sc*32];
__device__ uint32_t g_klo[(size_t)BHc*Sc*32];
__device__ uint32_t g_vhi[(size_t)BHc*(Sc/2)*64];
__device__ uint32_t g_vlo[(size_t)BHc*(Sc/2)*64];

__device__ __forceinline__ uint32_t smem_u32(const void* p){
    uint32_t a;
    asm("{ .reg .u64 t; cvta.to.shared.u64 t, %1; cvt.u32.u64 %0, t; }" : "=r"(a) : "l"(p));
    return a;
}
__device__ __forceinline__ void cp16(uint32_t dst, const void* src){
    asm volatile("cp.async.cg.shared.global [%0], [%1], 16;" :: "r"(dst), "l"(src));
}
#define CP_COMMIT() asm volatile("cp.async.commit_group;" ::: "memory")
#define CP_WAIT0()  asm volatile("cp.async.wait_group 0;" ::: "memory")

__device__ __forceinline__ uint32_t packb(float hi, float lo){
    uint32_t r;
    asm("cvt.rn.bf16x2.f32 %0, %1, %2;" : "=r"(r) : "f"(hi), "f"(lo));
    return r;
}
__device__ __forceinline__ float unpk_lo(uint32_t u){ return __uint_as_float(u << 16); }
__device__ __forceinline__ float unpk_hi(uint32_t u){ return __uint_as_float(u & 0xFFFF0000u); }
__device__ __forceinline__ void split_pair(float x0, float x1, uint32_t &h, uint32_t &l){
    h = packb(x1, x0);
    l = packb(x1 - unpk_hi(h), x0 - unpk_lo(h));
}
__device__ __forceinline__ void mma_bf16(float c[4], uint32_t a0,uint32_t a1,uint32_t a2,uint32_t a3,
                                         uint32_t b0,uint32_t b1){
    asm volatile("mma.sync.aligned.m16n8k16.row.col.f32.bf16.bf16.f32 "
        "{%0,%1,%2,%3}, {%4,%5,%6,%7}, {%8,%9}, {%0,%1,%2,%3};"
        : "+f"(c[0]),"+f"(c[1]),"+f"(c[2]),"+f"(c[3])
        : "r"(a0),"r"(a1),"r"(a2),"r"(a3),"r"(b0),"r"(b1));
}

// ---- prep: fp32 K/V -> packed bf16 hi/lo global buffers ----
__global__ __launch_bounds__(256)
void prep_split(const float* __restrict__ k, const float* __restrict__ v)
{
    int idx = blockIdx.x*256 + threadIdx.x;
    if (idx < BHc*Sc*16) {
        float4 x = ((const float4*)k)[(size_t)idx];
        uint32_t h0,l0,h1,l1;
        split_pair(x.x, x.y, h0, l0);
        split_pair(x.z, x.w, h1, l1);
        size_t o = ((size_t)(idx >> 4) << 5) + (size_t)((idx & 15) << 1);
        *(uint2*)&g_khi[o] = make_uint2(h0, h1);
        *(uint2*)&g_klo[o] = make_uint2(l0, l1);
    } else {
        int vi = idx - BHc*Sc*16;
        if (vi < BHc*(Sc/2)*16) {
            int kp_g = vi >> 4;
            int ch   = vi & 15;
            const float4* vp = (const float4*)v;
            float4 f0 = vp[(size_t)kp_g*32 + ch];
            float4 f1 = vp[(size_t)kp_g*32 + 16 + ch];
            uint32_t h0,l0,h1,l1,h2,l2,h3,l3;
            split_pair(f0.x, f1.x, h0, l0);
            split_pair(f0.y, f1.y, h1, l1);
            split_pair(f0.z, f1.z, h2, l2);
            split_pair(f0.w, f1.w, h3, l3);
            size_t o = (size_t)kp_g*64 + (size_t)ch*4;
            *(uint4*)&g_vhi[o] = make_uint4(h0,h1,h2,h3);
            *(uint4*)&g_vlo[o] = make_uint4(l0,l1,l2,l3);
        }
    }
}

__device__ __forceinline__ void stage_tile(uint32_t sb, int stage, int bh, int tile, int tid)
{
    const uint32_t dstK = sb + stage*PSTAGE;
    #pragma unroll
    for (int i = 0; i < 8; i++) {
        int f = tid + i*THREADS;
        int hl = f >> 10, r = f & 1023;
        int row = r >> 3, ch = r & 7;
        const uint32_t* src = (hl ? g_klo : g_khi)
            + ((size_t)(bh*Sc + tile*NT + row))*32 + (size_t)ch*4;
        cp16(dstK + hl*KBYTES + row*(KSTR*4) + ch*16, src);
    }
    const uint32_t dstV = sb + stage*PSTAGE + 2*KBYTES;
    #pragma unroll
    for (int i = 0; i < 8; i++) {
        int f = tid + i*THREADS;
        int hl = f >> 10, r = f & 1023;
        int kp = r >> 4, ch = r & 15;
        const uint32_t* src = (hl ? g_vlo : g_vhi)
            + ((size_t)(bh*(Sc/2) + tile*(NT/2) + kp))*64 + (size_t)ch*4;
        cp16(dstV + hl*VBYTES + kp*(VSTR*4) + ch*16, src);
    }
}

__global__ __launch_bounds__(THREADS, 1)
void attn_tc(const float* __restrict__ q, const float* __restrict__ mask,
             float* __restrict__ out, float* __restrict__ attn)
{
    extern __shared__ char smem[];
    float* MaskAll = (float*)(smem + OFF_MASKALL);
    const uint32_t sb = smem_u32(smem);

    const int tid  = threadIdx.x;
    const int w    = tid >> 5, lane = tid & 31;
    const int t    = lane & 3, qr = lane >> 2;
    const int bh   = blockIdx.x >> 4;
    const int mt   = blockIdx.x & 15;
    const int row0 = mt * MT;
    const int b    = bh / Hc;
    const size_t qkvBase = (size_t)bh * Sc * Dc;
    const int arow = 16*w + qr;           // warp-private q-row (and +8)

    // ---- prologue: stage tile 0 ----
    stage_tile(sb, 0, bh, 0, tid);
    CP_COMMIT();

    // ---- mask row -> smem (premultiplied by -1e9) ----
    {
        const float4* mg = (const float4*)(mask + b*Sc);
        #pragma unroll
        for (int i = 0; i < 2; i++) {
            int f = tid + i*THREADS;
            float4 m = mg[f];
            m.x *= -1e9f; m.y *= -1e9f; m.z *= -1e9f; m.w *= -1e9f;
            ((float4*)MaskAll)[f] = m;
        }
    }

    // ---- Q A-fragments in registers (loaded once, scaled by 1/8, hi/lo split) ----
    uint32_t qhi[4][4], qlo[4][4];
    {
        const float* qp = q + qkvBase + (size_t)row0 * Dc;
        #pragma unroll
        for (int s = 0; s < 4; s++) {
            float2 a = *(const float2*)&qp[(size_t)arow*Dc     + 16*s + 2*t];
            float2 bq= *(const float2*)&qp[(size_t)(arow+8)*Dc + 16*s + 2*t];
            float2 c = *(const float2*)&qp[(size_t)arow*Dc     + 16*s + 2*t + 8];
            float2 d = *(const float2*)&qp[(size_t)(arow+8)*Dc + 16*s + 2*t + 8];
            split_pair(a.x*0.125f, a.y*0.125f, qhi[s][0], qlo[s][0]);
            split_pair(bq.x*0.125f, bq.y*0.125f, qhi[s][1], qlo[s][1]);
            split_pair(c.x*0.125f, c.y*0.125f, qhi[s][2], qlo[s][2]);
            split_pair(d.x*0.125f, d.y*0.125f, qhi[s][3], qlo[s][3]);
        }
    }

    float Co[8][4];
    #pragma unroll
    for (int n = 0; n < 8; n++) { Co[n][0]=Co[n][1]=Co[n][2]=Co[n][3]=0.f; }
    float dsA = 0.f, dsB = 0.f;

    for (int tile = 0; tile < NKV; tile++) {
        const int cur = tile & 1;
        CP_WAIT0();
        __syncthreads();   // staged tile visible; prefetch buffer free (prev PV done)

        if (tile + 1 < NKV) {
            stage_tile(sb, cur ^ 1, bh, tile + 1, tid);
            CP_COMMIT();
        }

        const uint32_t* Khi = (const uint32_t*)(smem + cur*PSTAGE);
        const uint32_t* Klo = Khi + KBYTES/4;
        const uint32_t* Vhi = Khi + 2*(KBYTES/4);
        const uint32_t* Vlo = Khi + 2*(KBYTES/4) + VBYTES/4;

        // ---- QK^T: 3-term bf16 (qhi*khi + qhi*klo + qlo*khi) ----
        float S[16][4];
        #pragma unroll
        for (int j = 0; j < 16; j++) { S[j][0]=S[j][1]=S[j][2]=S[j][3]=0.f; }

        #pragma unroll
        for (int s = 0; s < 4; s++) {
            #pragma unroll
            for (int j = 0; j < 16; j++) {
                const uint32_t* kh = &Khi[(8*j + qr)*KSTR + 8*s + t];
                const uint32_t* kl = &Klo[(8*j + qr)*KSTR + 8*s + t];
                uint32_t bh0 = kh[0], bh1 = kh[4];
                uint32_t bl0 = kl[0], bl1 = kl[4];
                mma_bf16(S[j], qhi[s][0],qhi[s][1],qhi[s][2],qhi[s][3], bh0,bh1);
                mma_bf16(S[j], qhi[s][0],qhi[s][1],qhi[s][2],qhi[s][3], bl0,bl1);
                mma_bf16(S[j], qlo[s][0],qlo[s][1],qlo[s][2],qlo[s][3], bh0,bh1);
            }
        }

        // ---- fused epilogue + PV: per k-step s, exp/store/split then 24 mmas ----
        const float* Ms = MaskAll + tile*NT;
        float* abase  = attn + ((size_t)bh*Sc + row0 + arow)*Sc + (size_t)tile*NT;
        float* abase8 = abase + (size_t)8*Sc;
        #pragma unroll
        for (int s = 0; s < 8; s++) {
            float e[8];
            #pragma unroll
            for (int jj = 0; jj < 2; jj++) {
                const int j = 2*s + jj;
                float2 m = *(float2*)&Ms[8*j + 2*t];
                float e0 = __expf(S[j][0] + m.x);
                float e1 = __expf(S[j][1] + m.y);
                float e2 = __expf(S[j][2] + m.x);
                float e3 = __expf(S[j][3] + m.y);
                dsA += e0 + e1; dsB += e2 + e3;
                *(float2*)&abase[8*j + 2*t]  = make_float2(e0, e1);
                *(float2*)&abase8[8*j + 2*t] = make_float2(e2, e3);
                e[4*jj+0]=e0; e[4*jj+1]=e1; e[4*jj+2]=e2; e[4*jj+3]=e3;
            }
            uint32_t ah0,al0,ah1,al1,ah2,al2,ah3,al3;
            split_pair(e[0], e[1], ah0, al0);
            split_pair(e[2], e[3], ah1, al1);
            split_pair(e[4], e[5], ah2, al2);
            split_pair(e[6], e[7], ah3, al3);
            #pragma unroll
            for (int nb = 0; nb < 8; nb++) {
                const uint32_t* vh = &Vhi[(8*s + t)*VSTR + 8*nb + qr];
                const uint32_t* vl = &Vlo[(8*s + t)*VSTR + 8*nb + qr];
                uint32_t b0h = vh[0], b1h = vh[4*VSTR];
                uint32_t b0l = vl[0], b1l = vl[4*VSTR];
                mma_bf16(Co[nb], ah0,ah1,ah2,ah3, b0h,b1h);
                mma_bf16(Co[nb], ah0,ah1,ah2,ah3, b0l,b1l);
                mma_bf16(Co[nb], al0,al1,al2,al3, b0h,b1h);
            }
        }
    }

    // ---- finalize: quad-reduce denominators, normalize out ----
    dsA += __shfl_xor_sync(0xffffffffu, dsA, 1);
    dsA += __shfl_xor_sync(0xffffffffu, dsA, 2);
    dsB += __shfl_xor_sync(0xffffffffu, dsB, 1);
    dsB += __shfl_xor_sync(0xffffffffu, dsB, 2);
    float invA = 1.0f / dsA, invB = 1.0f / dsB;

    float* obase  = out + qkvBase + (size_t)(row0 + arow)*Dc;
    float* obase8 = obase + 8*Dc;
    #pragma unroll
    for (int n = 0; n < 8; n++) {
        *(float2*)&obase[8*n + 2*t]  = make_float2(Co[n][0]*invA, Co[n][1]*invA);
        *(float2*)&obase8[8*n + 2*t] = make_float2(Co[n][2]*invB, Co[n][3]*invB);
    }
    if (t == 0) {
        g_inv[bh*Sc + row0 + arow]     = invA;
        g_inv[bh*Sc + row0 + arow + 8] = invB;
    }
}

__global__ __launch_bounds__(256)
void attn_norm(float* __restrict__ attn)
{
    int row = blockIdx.x;
    float inv = g_inv[row];
    float4* p = (float4*)(attn + (size_t)row * Sc);
    int t = threadIdx.x;
    float4 a = p[t];
    a.x *= inv; a.y *= inv; a.z *= inv; a.w *= inv;
    p[t] = a;
    float4 c = p[t + 256];
    c.x *= inv; c.y *= inv; c.z *= inv; c.w *= inv;
    p[t + 256] = c;
}

extern "C" void kernel_launch(void* const* d_in, const int* in_sizes, int n_in,
                              void* d_out, int out_size)
{
    const float* q    = (const float*)d_in[0];
    const float* k    = (const float*)d_in[1];
    const float* v    = (const float*)d_in[2];
    const float* mask = (const float*)d_in[3];

    float* out  = (float*)d_out;
    float* attn = out + (size_t)Bc*Hc*Sc*Dc;

    const int prepTasks = BHc*Sc*16 + BHc*(Sc/2)*16;
    prep_split<<<(prepTasks + 255)/256, 256>>>(k, v);

    cudaFuncSetAttribute(attn_tc, cudaFuncAttributeMaxDynamicSharedMemorySize, SMEM_BYTES);
    attn_tc<<<BHc*16, THREADS, SMEM_BYTES>>>(q, mask, out, attn);
    attn_norm<<<BHc*Sc, 256>>>(attn);
}